// round 1
// baseline (speedup 1.0000x reference)
#include <cuda_runtime.h>

#define F_NUM 20000
#define H_NUM 40000
#define NALL  60000
#define E_NUM 640000
#define D_DIM 128
#define A_DIM 64
#define B_NUM 256
#define P_ROWS 32
#define KSPLIT 25
#define KCH (F_NUM / KSPLIT)   // 800

// ---- scratch (static device globals; no allocation) ----
__device__ float g_P1[F_NUM * A_DIM];       // feat_emb @ W_top
__device__ float g_P2[NALL * A_DIM];        // all_emb @ W_bot
__device__ float g_scores[E_NUM];
__device__ float g_context[F_NUM * D_DIM];
__device__ int   g_cp[E_NUM];
__device__ int   g_fci[E_NUM];
__device__ int   g_is32[2];
__device__ float g_partial[KSPLIT * B_NUM * D_DIM];

// ---------------------------------------------------------------------------
// Detect whether index buffers are int32 or int64.
// Probe the tail region interpreted as int64, but only indices < E/2 so we
// never read past an int32-sized buffer. If the data is int32, the high word
// of each probed 8-byte value is an index near the end of the array
// (sorted cp ~ 19999; fci random in [0,60000)) -> value >= 2^32 >= NALL.
// If the data is genuinely int64, every value is a valid index < NALL.
// ---------------------------------------------------------------------------
__global__ void detect_k(const void* cp, const void* fci) {
    if (threadIdx.x != 0 || blockIdx.x != 0) return;
    const long long* p = (const long long*)cp;
    long long m = 0;
    for (int j = 1; j <= 8; ++j) {
        long long v = p[E_NUM / 2 - j];
        if (v < 0) v = (1LL << 40);
        if (v > m) m = v;
    }
    g_is32[0] = (m >= (long long)NALL) ? 1 : 0;
    const long long* q = (const long long*)fci;
    m = 0;
    for (int j = 1; j <= 8; ++j) {
        long long v = q[E_NUM / 2 - j];
        if (v < 0) v = (1LL << 40);
        if (v > m) m = v;
    }
    g_is32[1] = (m >= (long long)NALL) ? 1 : 0;
}

__global__ void convert_k(const void* cp, const void* fci) {
    int e = blockIdx.x * blockDim.x + threadIdx.x;
    if (e >= E_NUM) return;
    int is0 = g_is32[0], is1 = g_is32[1];
    g_cp[e]  = is0 ? ((const int*)cp)[e]  : (int)((const long long*)cp)[e];
    g_fci[e] = is1 ? ((const int*)fci)[e] : (int)((const long long*)fci)[e];
}

// ---------------------------------------------------------------------------
// P kernel: P1[f][a] = sum_d feat[f][d]   * W[d][a]        (W rows 0..127)
//           P2[i][a] = sum_d allemb[i][d] * W[128+d][a]    (W rows 128..255)
// Block: 128 threads. a = tid&63 (output col), h = tid>>6 (d-half).
// Each thread holds its 64 W values in registers; embedding rows are read
// as broadcast float4 loads. Halves combined through shared memory.
// ---------------------------------------------------------------------------
__global__ __launch_bounds__(128) void p_k(const float* __restrict__ feat,
                                           const float* __restrict__ hid,
                                           const float* __restrict__ w) {
    const int tid = threadIdx.x;
    const int a = tid & 63;
    const int h = tid >> 6;

    const int NB1 = F_NUM / P_ROWS;             // 625 blocks for P1
    const bool reg2 = (blockIdx.x >= NB1);
    const int row0 = (reg2 ? (blockIdx.x - NB1) : blockIdx.x) * P_ROWS;
    const int wbase = reg2 ? 128 : 0;

    float wr[64];
#pragma unroll
    for (int j = 0; j < 64; ++j)
        wr[j] = w[(wbase + h * 64 + j) * A_DIM + a];

    __shared__ float sh[64];

    for (int r = 0; r < P_ROWS; ++r) {
        const int row = row0 + r;
        const float* src;
        float* dst;
        if (!reg2) {
            src = feat + (size_t)row * D_DIM;
            dst = g_P1 + (size_t)row * A_DIM;
        } else {
            src = (row < F_NUM) ? (feat + (size_t)row * D_DIM)
                                : (hid + (size_t)(row - F_NUM) * D_DIM);
            dst = g_P2 + (size_t)row * A_DIM;
        }
        const float4* s4 = (const float4*)src;
        float a0 = 0.f, a1 = 0.f, a2 = 0.f, a3 = 0.f;
#pragma unroll
        for (int j = 0; j < 16; ++j) {
            float4 v = s4[h * 16 + j];
            a0 += v.x * wr[4 * j + 0];
            a1 += v.y * wr[4 * j + 1];
            a2 += v.z * wr[4 * j + 2];
            a3 += v.w * wr[4 * j + 3];
        }
        float acc = (a0 + a1) + (a2 + a3);
        if (h) sh[a] = acc;
        __syncthreads();
        if (!h) dst[a] = acc + sh[a];
        __syncthreads();
    }
}

// ---------------------------------------------------------------------------
// S kernel: one warp per connection.
// score[e] = exp( sum_a tanh(P1[cp[e]][a] + P2[fci[e]][a] + b[a]) * u[a] ) * corr[e]
// ---------------------------------------------------------------------------
__global__ __launch_bounds__(256) void s_k(const float* __restrict__ bias,
                                           const float* __restrict__ u,
                                           const float* __restrict__ corr) {
    const int lane = threadIdx.x & 31;
    const int e = blockIdx.x * 8 + (threadIdx.x >> 5);
    if (e >= E_NUM) return;
    const int c = g_cp[e];
    const int fi = g_fci[e];
    const float* p1 = g_P1 + (size_t)c * A_DIM;
    const float* p2 = g_P2 + (size_t)fi * A_DIM;
    float h1 = p1[lane]      + p2[lane]      + bias[lane];
    float h2 = p1[lane + 32] + p2[lane + 32] + bias[lane + 32];
    float t = tanhf(h1) * u[lane] + tanhf(h2) * u[lane + 32];
#pragma unroll
    for (int o = 16; o; o >>= 1) t += __shfl_xor_sync(0xffffffffu, t, o);
    if (lane == 0) g_scores[e] = expf(t) * corr[e];
}

// ---------------------------------------------------------------------------
// C kernel: one warp per feature segment (cp is sorted).
// context[f] = (sum_e s[e] * emb[fci[e]]) / (sum_e s[e])  over segment f.
// Deterministic: purely in-warp accumulation, no atomics.
// ---------------------------------------------------------------------------
__global__ __launch_bounds__(256) void c_k(const float* __restrict__ feat,
                                           const float* __restrict__ hid) {
    const int lane = threadIdx.x & 31;
    const int f = blockIdx.x * 8 + (threadIdx.x >> 5);
    if (f >= F_NUM) return;

    int lo, hiN;
    {
        int l = 0, r = E_NUM;
        while (l < r) { int m = (l + r) >> 1; if (g_cp[m] < f) l = m + 1; else r = m; }
        lo = l;
        r = E_NUM;
        while (l < r) { int m = (l + r) >> 1; if (g_cp[m] < f + 1) l = m + 1; else r = m; }
        hiN = l;
    }

    float4 acc = make_float4(0.f, 0.f, 0.f, 0.f);
    float den = 0.f;
    for (int e = lo; e < hiN; ++e) {
        const float s = g_scores[e];
        const int fi = g_fci[e];
        const float* src = (fi < F_NUM) ? (feat + (size_t)fi * D_DIM)
                                        : (hid + (size_t)(fi - F_NUM) * D_DIM);
        const float4 v = ((const float4*)src)[lane];
        acc.x += s * v.x; acc.y += s * v.y; acc.z += s * v.z; acc.w += s * v.w;
        den += s;
    }
    const float inv = (den != 0.f) ? (1.f / den) : 0.f;
    float4 o = make_float4(acc.x * inv, acc.y * inv, acc.z * inv, acc.w * inv);
    ((float4*)(g_context + (size_t)f * D_DIM))[lane] = o;
}

// ---------------------------------------------------------------------------
// G kernels: out[B=256, D=128] = values[B, F] @ context[F, D].
// Split-K into deterministic partials, then reduce.
// Block: 16 b-rows x 128 d, 800-k slice. values read as float4 over k.
// ---------------------------------------------------------------------------
__global__ __launch_bounds__(256) void g1_k(const float* __restrict__ values) {
    const int tid = threadIdx.x;
    const int d = tid & 127;
    const int bh = tid >> 7;
    const int b0 = blockIdx.x * 16 + bh * 8;
    const int k0 = blockIdx.y * KCH;

    float acc[8];
#pragma unroll
    for (int i = 0; i < 8; ++i) acc[i] = 0.f;

    for (int k = k0; k < k0 + KCH; k += 4) {
        const float c0 = g_context[(size_t)(k + 0) * D_DIM + d];
        const float c1 = g_context[(size_t)(k + 1) * D_DIM + d];
        const float c2 = g_context[(size_t)(k + 2) * D_DIM + d];
        const float c3 = g_context[(size_t)(k + 3) * D_DIM + d];
#pragma unroll
        for (int i = 0; i < 8; ++i) {
            const float4 v = *(const float4*)(values + (size_t)(b0 + i) * F_NUM + k);
            acc[i] += v.x * c0 + v.y * c1 + v.z * c2 + v.w * c3;
        }
    }
    float* part = g_partial + (size_t)blockIdx.y * (B_NUM * D_DIM);
#pragma unroll
    for (int i = 0; i < 8; ++i) part[(size_t)(b0 + i) * D_DIM + d] = acc[i];
}

__global__ __launch_bounds__(256) void g2_k(float* __restrict__ out) {
    const int i = blockIdx.x * blockDim.x + threadIdx.x;
    if (i >= B_NUM * D_DIM) return;
    float s = 0.f;
#pragma unroll
    for (int j = 0; j < KSPLIT; ++j) s += g_partial[(size_t)j * (B_NUM * D_DIM) + i];
    out[i] = s;
}

// ---------------------------------------------------------------------------
extern "C" void kernel_launch(void* const* d_in, const int* in_sizes, int n_in,
                              void* d_out, int out_size) {
    const float* values = (const float*)d_in[0];
    const float* feat   = (const float*)d_in[1];
    const float* hid    = (const float*)d_in[2];
    const float* w      = (const float*)d_in[3];
    const float* bias   = (const float*)d_in[4];
    const float* u      = (const float*)d_in[5];
    const float* corr   = (const float*)d_in[6];
    const void*  cp     = d_in[7];
    const void*  fci    = d_in[8];
    float* out = (float*)d_out;

    detect_k<<<1, 32>>>(cp, fci);
    convert_k<<<(E_NUM + 255) / 256, 256>>>(cp, fci);
    p_k<<<(F_NUM + NALL) / P_ROWS, 128>>>(feat, hid, w);
    s_k<<<E_NUM / 8, 256>>>(bias, u, corr);
    c_k<<<F_NUM / 8, 256>>>(feat, hid);
    g1_k<<<dim3(16, KSPLIT), 256>>>(values);
    g2_k<<<(B_NUM * D_DIM + 255) / 256, 256>>>(out);
}

// round 2
// speedup vs baseline: 1.1379x; 1.1379x over previous
#include <cuda_runtime.h>

#define F_NUM 20000
#define H_NUM 40000
#define NALL  60000
#define E_NUM 640000
#define D_DIM 128
#define A_DIM 64
#define B_NUM 256
#define P_ROWS 32
#define KSPLIT 25
#define KCH (F_NUM / KSPLIT)   // 800

// ---- scratch (static device globals; no allocation) ----
__device__ float g_P1[F_NUM * A_DIM];       // feat_emb @ W_top
__device__ float g_P2[NALL * A_DIM];        // all_emb @ W_bot
__device__ float g_scores[E_NUM];
__device__ float g_context[F_NUM * D_DIM];
__device__ int   g_cp[E_NUM];
__device__ int   g_fci[E_NUM];
__device__ int   g_is32[2];
__device__ float g_partial[KSPLIT * B_NUM * D_DIM];

__device__ __forceinline__ float tanh_hw(float x) {
    float y;
    asm("tanh.approx.f32 %0, %1;" : "=f"(y) : "f"(x));
    return y;
}

// ---------------------------------------------------------------------------
// Detect whether index buffers are int32 or int64 (probe tail as int64; int32
// data yields high-word >= NALL).
// ---------------------------------------------------------------------------
__global__ void detect_k(const void* cp, const void* fci) {
    if (threadIdx.x != 0 || blockIdx.x != 0) return;
    const long long* p = (const long long*)cp;
    long long m = 0;
    for (int j = 1; j <= 8; ++j) {
        long long v = p[E_NUM / 2 - j];
        if (v < 0) v = (1LL << 40);
        if (v > m) m = v;
    }
    g_is32[0] = (m >= (long long)NALL) ? 1 : 0;
    const long long* q = (const long long*)fci;
    m = 0;
    for (int j = 1; j <= 8; ++j) {
        long long v = q[E_NUM / 2 - j];
        if (v < 0) v = (1LL << 40);
        if (v > m) m = v;
    }
    g_is32[1] = (m >= (long long)NALL) ? 1 : 0;
}

__global__ void convert_k(const void* cp, const void* fci) {
    int e = blockIdx.x * blockDim.x + threadIdx.x;
    if (e >= E_NUM) return;
    int is0 = g_is32[0], is1 = g_is32[1];
    g_cp[e]  = is0 ? ((const int*)cp)[e]  : (int)((const long long*)cp)[e];
    g_fci[e] = is1 ? ((const int*)fci)[e] : (int)((const long long*)fci)[e];
}

// ---------------------------------------------------------------------------
// P kernel: P1[f][a] = sum_d feat[f][d]   * W[d][a]        (W rows 0..127)
//           P2[i][a] = sum_d allemb[i][d] * W[128+d][a]    (W rows 128..255)
// 128 threads: a = tid&63, h = tid>>6 (d-half). 64 W values per thread in
// registers. 8 rows accumulated per __syncthreads pair (BAR amortization).
// ---------------------------------------------------------------------------
__global__ __launch_bounds__(128) void p_k(const float* __restrict__ feat,
                                           const float* __restrict__ hid,
                                           const float* __restrict__ w) {
    const int tid = threadIdx.x;
    const int a = tid & 63;
    const int h = tid >> 6;

    const int NB1 = F_NUM / P_ROWS;             // 625 blocks for P1
    const bool reg2 = (blockIdx.x >= NB1);
    const int row0 = (reg2 ? (blockIdx.x - NB1) : blockIdx.x) * P_ROWS;
    const int wbase = reg2 ? 128 : 0;

    float wr[64];
#pragma unroll
    for (int j = 0; j < 64; ++j)
        wr[j] = w[(wbase + h * 64 + j) * A_DIM + a];

    __shared__ float sh[8][64];

    for (int r0 = 0; r0 < P_ROWS; r0 += 8) {
        float acc[8];
#pragma unroll
        for (int rr = 0; rr < 8; ++rr) {
            const int row = row0 + r0 + rr;
            const float* src;
            if (!reg2) {
                src = feat + (size_t)row * D_DIM;
            } else {
                src = (row < F_NUM) ? (feat + (size_t)row * D_DIM)
                                    : (hid + (size_t)(row - F_NUM) * D_DIM);
            }
            const float4* s4 = (const float4*)src;
            float a0 = 0.f, a1 = 0.f, a2 = 0.f, a3 = 0.f;
#pragma unroll
            for (int j = 0; j < 16; ++j) {
                float4 v = s4[h * 16 + j];
                a0 += v.x * wr[4 * j + 0];
                a1 += v.y * wr[4 * j + 1];
                a2 += v.z * wr[4 * j + 2];
                a3 += v.w * wr[4 * j + 3];
            }
            acc[rr] = (a0 + a1) + (a2 + a3);
        }
        if (h) {
#pragma unroll
            for (int rr = 0; rr < 8; ++rr) sh[rr][a] = acc[rr];
        }
        __syncthreads();
        if (!h) {
#pragma unroll
            for (int rr = 0; rr < 8; ++rr) {
                const int row = row0 + r0 + rr;
                float* dst = reg2 ? (g_P2 + (size_t)row * A_DIM)
                                  : (g_P1 + (size_t)row * A_DIM);
                dst[a] = acc[rr] + sh[rr][a];
            }
        }
        __syncthreads();
    }
}

// ---------------------------------------------------------------------------
// S kernel: one THREAD per connection (lane-per-edge).
// score[e] = exp( sum_a tanh(P1[cp[e]][a] + P2[fci[e]][a] + b[a]) * u[a] ) * corr[e]
// Hardware tanh.approx + __expf; bias/u staged in smem (uniform broadcast).
// ---------------------------------------------------------------------------
__global__ __launch_bounds__(256) void s_k(const float* __restrict__ bias,
                                           const float* __restrict__ u,
                                           const float* __restrict__ corr) {
    __shared__ float4 sb[16];
    __shared__ float4 su[16];
    const int tid = threadIdx.x;
    if (tid < 16) {
        sb[tid] = ((const float4*)bias)[tid];
        su[tid] = ((const float4*)u)[tid];
    }
    __syncthreads();

    const int e = blockIdx.x * 256 + tid;
    if (e >= E_NUM) return;
    const int c = g_cp[e];
    const int fi = g_fci[e];
    const float4* p1 = (const float4*)(g_P1 + (size_t)c * A_DIM);
    const float4* p2 = (const float4*)(g_P2 + (size_t)fi * A_DIM);

    float t = 0.f;
#pragma unroll
    for (int j = 0; j < 16; ++j) {
        const float4 x = p1[j];
        const float4 y = p2[j];
        const float4 b = sb[j];
        const float4 q = su[j];
        t += tanh_hw(x.x + y.x + b.x) * q.x;
        t += tanh_hw(x.y + y.y + b.y) * q.y;
        t += tanh_hw(x.z + y.z + b.z) * q.z;
        t += tanh_hw(x.w + y.w + b.w) * q.w;
    }
    g_scores[e] = __expf(t) * corr[e];
}

// ---------------------------------------------------------------------------
// C kernel: one warp per feature segment (cp is sorted).
// context[f] = (sum_e s[e] * emb[fci[e]]) / (sum_e s[e])  over segment f.
// ---------------------------------------------------------------------------
__global__ __launch_bounds__(256) void c_k(const float* __restrict__ feat,
                                           const float* __restrict__ hid) {
    const int lane = threadIdx.x & 31;
    const int f = blockIdx.x * 8 + (threadIdx.x >> 5);
    if (f >= F_NUM) return;

    int lo, hiN;
    {
        int l = 0, r = E_NUM;
        while (l < r) { int m = (l + r) >> 1; if (g_cp[m] < f) l = m + 1; else r = m; }
        lo = l;
        r = E_NUM;
        while (l < r) { int m = (l + r) >> 1; if (g_cp[m] < f + 1) l = m + 1; else r = m; }
        hiN = l;
    }

    float4 acc = make_float4(0.f, 0.f, 0.f, 0.f);
    float den = 0.f;
    for (int e = lo; e < hiN; ++e) {
        const float s = g_scores[e];
        const int fi = g_fci[e];
        const float* src = (fi < F_NUM) ? (feat + (size_t)fi * D_DIM)
                                        : (hid + (size_t)(fi - F_NUM) * D_DIM);
        const float4 v = ((const float4*)src)[lane];
        acc.x += s * v.x; acc.y += s * v.y; acc.z += s * v.z; acc.w += s * v.w;
        den += s;
    }
    const float inv = (den != 0.f) ? (1.f / den) : 0.f;
    float4 o = make_float4(acc.x * inv, acc.y * inv, acc.z * inv, acc.w * inv);
    ((float4*)(g_context + (size_t)f * D_DIM))[lane] = o;
}

// ---------------------------------------------------------------------------
// G kernels: out[B=256, D=128] = values[B, F] @ context[F, D].
// Split-K deterministic partials + reduction.
// ---------------------------------------------------------------------------
__global__ __launch_bounds__(256) void g1_k(const float* __restrict__ values) {
    const int tid = threadIdx.x;
    const int d = tid & 127;
    const int bh = tid >> 7;
    const int b0 = blockIdx.x * 16 + bh * 8;
    const int k0 = blockIdx.y * KCH;

    float acc[8];
#pragma unroll
    for (int i = 0; i < 8; ++i) acc[i] = 0.f;

    for (int k = k0; k < k0 + KCH; k += 4) {
        const float c0 = g_context[(size_t)(k + 0) * D_DIM + d];
        const float c1 = g_context[(size_t)(k + 1) * D_DIM + d];
        const float c2 = g_context[(size_t)(k + 2) * D_DIM + d];
        const float c3 = g_context[(size_t)(k + 3) * D_DIM + d];
#pragma unroll
        for (int i = 0; i < 8; ++i) {
            const float4 v = *(const float4*)(values + (size_t)(b0 + i) * F_NUM + k);
            acc[i] += v.x * c0 + v.y * c1 + v.z * c2 + v.w * c3;
        }
    }
    float* part = g_partial + (size_t)blockIdx.y * (B_NUM * D_DIM);
#pragma unroll
    for (int i = 0; i < 8; ++i) part[(size_t)(b0 + i) * D_DIM + d] = acc[i];
}

__global__ __launch_bounds__(256) void g2_k(float* __restrict__ out) {
    const int i = blockIdx.x * blockDim.x + threadIdx.x;
    if (i >= B_NUM * D_DIM) return;
    float s = 0.f;
#pragma unroll
    for (int j = 0; j < KSPLIT; ++j) s += g_partial[(size_t)j * (B_NUM * D_DIM) + i];
    out[i] = s;
}

// ---------------------------------------------------------------------------
extern "C" void kernel_launch(void* const* d_in, const int* in_sizes, int n_in,
                              void* d_out, int out_size) {
    const float* values = (const float*)d_in[0];
    const float* feat   = (const float*)d_in[1];
    const float* hid    = (const float*)d_in[2];
    const float* w      = (const float*)d_in[3];
    const float* bias   = (const float*)d_in[4];
    const float* u      = (const float*)d_in[5];
    const float* corr   = (const float*)d_in[6];
    const void*  cp     = d_in[7];
    const void*  fci    = d_in[8];
    float* out = (float*)d_out;

    detect_k<<<1, 32>>>(cp, fci);
    convert_k<<<(E_NUM + 255) / 256, 256>>>(cp, fci);
    p_k<<<(F_NUM + NALL) / P_ROWS, 128>>>(feat, hid, w);
    s_k<<<(E_NUM + 255) / 256, 256>>>(bias, u, corr);
    c_k<<<F_NUM / 8, 256>>>(feat, hid);
    g1_k<<<dim3(16, KSPLIT), 256>>>(values);
    g2_k<<<(B_NUM * D_DIM + 255) / 256, 256>>>(out);
}